// round 1
// baseline (speedup 1.0000x reference)
#include <cuda_runtime.h>

#define DIM   512
#define CDIM  12
#define NTOK  16384
#define CSIZE 4096

#define OUT_OFF_IDX (NTOK * DIM)            // 8388608
#define OUT_OFF_AUX (OUT_OFF_IDX + NTOK)    // 8404992
#define LOG_EPS_NEG 11.512925464970229f     // -ln(1e-5)

// ---- device scratch (no allocations allowed) ----
__device__ float g_xp[CDIM * NTOK];   // xp transposed: [c][tok]
__device__ float g_avg[CSIZE];        // sum over samples of per-code prob
__device__ float g_pse;               // sum over samples of per-sample entropy

// ---------------------------------------------------------------------------
// Zero the accumulators (graph replays reuse them).
// ---------------------------------------------------------------------------
__global__ void initK() {
    int t = blockIdx.x * blockDim.x + threadIdx.x;
    if (t < CSIZE) g_avg[t] = 0.f;
    if (t == CSIZE) g_pse = 0.f;
}

// ---------------------------------------------------------------------------
// Main fused kernel: in-proj + quantize + index + out-proj.
// grid 256 x block 512; each warp handles 4 consecutive tokens.
// Shared: w_in [12][512] + w_out^T [12][512] = 48 KB exactly.
// ---------------------------------------------------------------------------
__global__ void __launch_bounds__(512, 1)
mainK(const float* __restrict__ x,
      const float* __restrict__ w_in,
      const float* __restrict__ b_in,
      const float* __restrict__ w_out,
      const float* __restrict__ b_out,
      float* __restrict__ out)
{
    extern __shared__ float sm[];
    float* s_win  = sm;               // [c][d]
    float* s_wout = sm + CDIM * DIM;  // transposed: [c][d]

    // stage weights
    for (int i = threadIdx.x; i < CDIM * DIM; i += blockDim.x) {
        s_win[i] = w_in[i];
        int d = i / CDIM, c = i % CDIM;           // w_out is [512][12]
        s_wout[c * DIM + d] = w_out[i];
    }
    __syncthreads();

    const int wid  = threadIdx.x >> 5;
    const int lane = threadIdx.x & 31;
    const int gw   = blockIdx.x * (blockDim.x >> 5) + wid;   // 0..4095
    const int tok0 = gw * 4;

    float bin[CDIM];
#pragma unroll
    for (int c = 0; c < CDIM; c++) bin[c] = b_in[c];

    const float4* X4  = (const float4*)x;
    float4*       O4  = (float4*)out;
    const float4* W4  = (const float4*)s_win;
    const float4* WO4 = (const float4*)s_wout;
    const float4* BO4 = (const float4*)b_out;   // small, L1-resident

    // ---- in-projection: xp[t][c] = <x[t], w_in[c]> + b_in[c] ----
    float acc[4][CDIM];
#pragma unroll
    for (int t = 0; t < 4; t++)
#pragma unroll
        for (int c = 0; c < CDIM; c++) acc[t][c] = 0.f;

#pragma unroll
    for (int i = 0; i < 4; i++) {
        const int off = i * 32 + lane;            // float4 index within 128
        float4 w[CDIM];
#pragma unroll
        for (int c = 0; c < CDIM; c++) w[c] = W4[c * 128 + off];
#pragma unroll
        for (int t = 0; t < 4; t++) {
            float4 xv = X4[(size_t)(tok0 + t) * 128 + off];
#pragma unroll
            for (int c = 0; c < CDIM; c++) {
                acc[t][c] += xv.x * w[c].x + xv.y * w[c].y
                           + xv.z * w[c].z + xv.w * w[c].w;
            }
        }
    }

    // warp butterfly reduction -> every lane holds full xp
#pragma unroll
    for (int t = 0; t < 4; t++)
#pragma unroll
        for (int c = 0; c < CDIM; c++) {
            float v = acc[t][c];
            v += __shfl_xor_sync(0xffffffffu, v, 16);
            v += __shfl_xor_sync(0xffffffffu, v, 8);
            v += __shfl_xor_sync(0xffffffffu, v, 4);
            v += __shfl_xor_sync(0xffffffffu, v, 2);
            v += __shfl_xor_sync(0xffffffffu, v, 1);
            acc[t][c] = v + bin[c];
        }

    // ---- indices ----
    int idx[4];
#pragma unroll
    for (int t = 0; t < 4; t++) {
        int ix = 0;
#pragma unroll
        for (int c = 0; c < CDIM; c++)
            if (acc[t][c] > 0.f) ix |= 1 << (11 - c);
        idx[t] = ix;
    }

    // lane 0: spill xp to scratch (transposed) + write indices (as float)
    if (lane == 0) {
#pragma unroll
        for (int t = 0; t < 4; t++) {
            out[OUT_OFF_IDX + tok0 + t] = (float)idx[t];
#pragma unroll
            for (int c = 0; c < CDIM; c++)
                g_xp[c * NTOK + tok0 + t] = acc[t][c];
        }
    }

    // overwrite acc with quantized values (+-1) — x_st == quantized numerically
#pragma unroll
    for (int t = 0; t < 4; t++)
#pragma unroll
        for (int c = 0; c < CDIM; c++)
            acc[t][c] = acc[t][c] > 0.f ? 1.f : -1.f;

    // ---- out-projection: out[t][d] = b_out[d] + sum_c q[t][c] * w_out[d][c]
#pragma unroll
    for (int i = 0; i < 4; i++) {
        const int off = i * 32 + lane;
        float4 w[CDIM];
#pragma unroll
        for (int c = 0; c < CDIM; c++) w[c] = WO4[c * 128 + off];
        float4 bo = BO4[off];
#pragma unroll
        for (int t = 0; t < 4; t++) {
            float4 o = bo;
#pragma unroll
            for (int c = 0; c < CDIM; c++) {
                o.x += acc[t][c] * w[c].x;
                o.y += acc[t][c] * w[c].y;
                o.z += acc[t][c] * w[c].z;
                o.w += acc[t][c] * w[c].w;
            }
            O4[(size_t)(tok0 + t) * 128 + off] = o;
        }
    }
}

// ---------------------------------------------------------------------------
// Entropy kernel: one thread per token. The 4096-code softmax factorizes
// into 12 independent binaries; only "active" dims (t_c = exp(-400|xp|) >
// 1e-9) carry mass distinguishable at f32. Enumerate 2^k codes (k small).
//   p_S = (prod_{c in S} t_c) / Z,   -log p_S = A_S + log Z
//   pse += p_S * min(-log p_S, -log eps)    [matches jnp clip semantics]
//   g_avg[code] += p_S
// ---------------------------------------------------------------------------
__global__ void entK() {
    int tok = blockIdx.x * blockDim.x + threadIdx.x;
    float pse = 0.f;
    if (tok < NTOK) {
        float t_a[CDIM], a_a[CDIM];
        int   m_a[CDIM];
        int   k = 0, idx0 = 0;
        float Z = 1.f;
#pragma unroll
        for (int c = 0; c < CDIM; c++) {
            float xp = g_xp[c * NTOK + tok];
            float a  = 400.f * fabsf(xp);
            if (xp > 0.f) idx0 |= 1 << (11 - c);
            float tt = expf(-a);
            if (tt > 1e-9f) {
                t_a[k] = tt; a_a[k] = a; m_a[k] = 1 << (11 - c);
                k++;
                Z *= (1.f + tt);
            }
        }
        float logZ = logf(Z);
        float invZ = 1.f / Z;
        int n = 1 << k;
        for (int s = 0; s < n; s++) {
            float p = invZ, A = logZ;
            int ix = idx0;
            for (int j = 0; j < k; j++) {
                if ((s >> j) & 1) { p *= t_a[j]; A += a_a[j]; ix ^= m_a[j]; }
            }
            pse += p * fminf(A, LOG_EPS_NEG);
            atomicAdd(&g_avg[ix], p);
        }
    }
    // block reduce pse
    __shared__ float red[256];
    red[threadIdx.x] = pse;
    __syncthreads();
    for (int s = 128; s > 0; s >>= 1) {
        if (threadIdx.x < (unsigned)s) red[threadIdx.x] += red[threadIdx.x + s];
        __syncthreads();
    }
    if (threadIdx.x == 0) atomicAdd(&g_pse, red[0]);
}

// ---------------------------------------------------------------------------
// Finalize: codebook entropy of avg_prob + aux loss.
// ---------------------------------------------------------------------------
__global__ void finK(float* __restrict__ out) {
    __shared__ float red[256];
    const float inv = 1.f / (float)NTOK;
    float ce = 0.f;
    for (int i = threadIdx.x; i < CSIZE; i += 256) {
        float ap = g_avg[i] * inv;
        ce += -ap * logf(fmaxf(ap, 1e-5f));
    }
    red[threadIdx.x] = ce;
    __syncthreads();
    for (int s = 128; s > 0; s >>= 1) {
        if (threadIdx.x < (unsigned)s) red[threadIdx.x] += red[threadIdx.x + s];
        __syncthreads();
    }
    if (threadIdx.x == 0) {
        float aux = (g_pse * inv - red[0]) * 0.1f;
        out[OUT_OFF_AUX] = aux;
    }
}

// ---------------------------------------------------------------------------
extern "C" void kernel_launch(void* const* d_in, const int* in_sizes, int n_in,
                              void* d_out, int out_size)
{
    const float* x     = (const float*)d_in[0];
    const float* w_in  = (const float*)d_in[1];
    const float* b_in  = (const float*)d_in[2];
    const float* w_out = (const float*)d_in[3];
    const float* b_out = (const float*)d_in[4];
    float* out = (float*)d_out;

    const size_t smem = (size_t)(2 * CDIM * DIM) * sizeof(float);  // 49152 B

    initK<<<5, 1024>>>();
    mainK<<<256, 512, smem>>>(x, w_in, b_in, w_out, b_out, out);
    entK<<<64, 256>>>();
    finK<<<1, 256>>>(out);
}